// round 15
// baseline (speedup 1.0000x reference)
#include <cuda_runtime.h>
#include <cuda_fp16.h>
#include <cstdint>
#include <cstddef>

// Problem constants
#define BROWS 16384
#define INDIM 1024
#define HID   4096
#define ODIM  384
#define NGRP  6
#define POOL  64
#define TOPK  2

#define RSCALE   2048.0f          // 2^11: residual pre-scale
#define RSCALE_I 0.00048828125f   // 2^-11

// ---------------- scratch (device globals; no allocation allowed) ----------------
__device__ __align__(16) __half g_qh[(size_t)BROWS * INDIM];
__device__ __align__(16) __half g_ql[(size_t)BROWS * INDIM];
__device__ __align__(16) __half g_w1h[(size_t)HID * INDIM];   // Wt [N][K] fp16 planes
__device__ __align__(16) __half g_w1l[(size_t)HID * INDIM];
__device__ __align__(16) __half g_w2h[(size_t)HID * HID];
__device__ __align__(16) __half g_w2l[(size_t)HID * HID];
__device__ __align__(16) __half g_w3h[(size_t)ODIM * HID];
__device__ __align__(16) __half g_w3l[(size_t)ODIM * HID];
__device__ __align__(16) __half g_h1h[(size_t)BROWS * HID];
__device__ __align__(16) __half g_h1l[(size_t)BROWS * HID];
__device__ __align__(16) __half g_h2h[(size_t)BROWS * HID];
__device__ __align__(16) __half g_h2l[(size_t)BROWS * HID];
// fp32 transposed activations/query for the FFMA sub-GEMM: [K][M]
__device__ __align__(16) float g_qt32[(size_t)INDIM * BROWS];
__device__ __align__(16) float g_h1t[(size_t)HID * BROWS];
__device__ __align__(16) float g_h2t[(size_t)HID * BROWS];

// ---------------- helpers ----------------
__device__ __forceinline__ float gelu_f(float x) {
    float t = tanhf(0.7978845608028654f * (x + 0.044715f * x * x * x));
    return 0.5f * x * (1.0f + t);
}
__device__ __forceinline__ float sig2_f(float x) {
    return 2.0f / (1.0f + expf(-x));
}

#define CP_ASYNC16(dst, src) \
    asm volatile("cp.async.cg.shared.global [%0], [%1], 16;\n" :: "r"(dst), "l"(src) : "memory")
#define CP_COMMIT() asm volatile("cp.async.commit_group;\n" ::: "memory")
#define CP_WAIT2()  asm volatile("cp.async.wait_group 2;\n" ::: "memory")
#define CP_WAIT1()  asm volatile("cp.async.wait_group 1;\n" ::: "memory")
#define CP_WAIT0()  asm volatile("cp.async.wait_group 0;\n" ::: "memory")

#define MMA_F16(C0, C1, C2, C3, A0, A1, A2, A3, B0, B1) \
    asm volatile( \
        "mma.sync.aligned.m16n8k16.row.col.f32.f16.f16.f32 " \
        "{%0,%1,%2,%3}, {%4,%5,%6,%7}, {%8,%9}, {%0,%1,%2,%3};\n" \
        : "+f"(C0), "+f"(C1), "+f"(C2), "+f"(C3) \
        : "r"(A0), "r"(A1), "r"(A2), "r"(A3), "r"(B0), "r"(B1))

// ---------------- smem: 4 stages, BK=32 ----------------
// stage: Ah[128][40h] Al | Bh[96][40h] Bl | A32t[32][128]f | B32[32][32]f
#define PB      80
#define OFF_AH  0
#define OFF_AL  10240
#define OFF_BH  20480
#define OFF_BL  28160
#define OFF_A32 35840
#define OFF_B32 52224
#define STG     56320
#define GSMEM   (4 * STG)   // 225280 B (<= 227KB cap; also covers 128x129 f32 staging 66048)

// ---------------- hybrid GEMM: tensor 3-product (cols 0..95) + fp32 FFMA (cols 96..127) ----
template <int EPI>
__global__ __launch_bounds__(256, 1) void gemm_hy(
    const __half* __restrict__ Ah_g, const __half* __restrict__ Al_g,
    const __half* __restrict__ Bh_g, const __half* __restrict__ Bl_g,
    const float* __restrict__ At32,   // [K][BROWS] fp32 (transposed A)
    const float* __restrict__ Bw32,   // [K][N] fp32 (original weights)
    const float* __restrict__ bias,
    __half* __restrict__ Ohi, __half* __restrict__ Olo, float* __restrict__ Oht,
    float* __restrict__ Oc, float* __restrict__ Tv, float* __restrict__ Ti,
    int N, int K, int nk)
{
    extern __shared__ char sm[];
    const uint32_t sbase = (uint32_t)__cvta_generic_to_shared(sm);

    const int tid  = threadIdx.x;
    const int lane = tid & 31;
    const int warp = tid >> 5;
    const int wm = warp & 1;      // 2 warp rows (64 each)
    const int wn = warp >> 1;     // 4 warp cols (24 each, tensor region 96)
    const int gid = lane >> 2;
    const int tq  = lane & 3;

    const int m0 = blockIdx.y * 128;
    const int n0 = blockIdx.x * 128;

    // FFMA mapping: 16 outputs/thread = 4 rows x 4 cols over rows 0..127, cols 96..127
    const int fr0 = warp * 16 + (lane >> 3) * 4;
    const int fc0 = (lane & 7) * 4;    // within 32-col FFMA region

    auto load_stage = [&](int kt, int s) {
        const uint32_t st = sbase + (uint32_t)s * STG;
        const int kg = kt * 32;
#pragma unroll
        for (int p = 0; p < 12; p++) {
            const int c = p * 256 + tid;    // 0..3071
            if (c < 512) {                  // Ah: 128 rows x 4 chunks
                const int row = c >> 2, kc = c & 3;
                CP_ASYNC16(st + OFF_AH + (uint32_t)(row * PB + kc * 16),
                           Ah_g + (size_t)(m0 + row) * K + kg + kc * 8);
            } else if (c < 1024) {          // Al
                const int c2 = c - 512, row = c2 >> 2, kc = c2 & 3;
                CP_ASYNC16(st + OFF_AL + (uint32_t)(row * PB + kc * 16),
                           Al_g + (size_t)(m0 + row) * K + kg + kc * 8);
            } else if (c < 1408) {          // Bh: 96 rows x 4 chunks
                const int c2 = c - 1024, row = c2 >> 2, kc = c2 & 3;
                CP_ASYNC16(st + OFF_BH + (uint32_t)(row * PB + kc * 16),
                           Bh_g + (size_t)(n0 + row) * K + kg + kc * 8);
            } else if (c < 1792) {          // Bl
                const int c2 = c - 1408, row = c2 >> 2, kc = c2 & 3;
                CP_ASYNC16(st + OFF_BL + (uint32_t)(row * PB + kc * 16),
                           Bl_g + (size_t)(n0 + row) * K + kg + kc * 8);
            } else if (c < 2816) {          // A32t: 32 k x 32 chunks (128 floats)
                const int c2 = c - 1792, k = c2 >> 5, m4 = c2 & 31;
                CP_ASYNC16(st + OFF_A32 + (uint32_t)(k * 512 + m4 * 16),
                           At32 + (size_t)(kg + k) * BROWS + m0 + m4 * 4);
            } else {                        // B32: 32 k x 8 chunks (32 floats)
                const int c2 = c - 2816, k = c2 >> 3, n4 = c2 & 7;
                CP_ASYNC16(st + OFF_B32 + (uint32_t)(k * 128 + n4 * 16),
                           Bw32 + (size_t)(kg + k) * N + n0 + 96 + n4 * 4);
            }
        }
        CP_COMMIT();
    };

    float cc[4][3][4];   // ah*bh (tensor cols 0..95)
    float s2[4][3][4];   // cross terms (pre-scaled 2^11)
    float fa[4][4];      // FFMA accumulators (cols 96..127)
#pragma unroll
    for (int a = 0; a < 4; a++) {
#pragma unroll
        for (int b = 0; b < 3; b++)
#pragma unroll
            for (int d = 0; d < 4; d++) { cc[a][b][d] = 0.0f; s2[a][b][d] = 0.0f; }
#pragma unroll
        for (int d = 0; d < 4; d++) fa[a][d] = 0.0f;
    }

    load_stage(0, 0);
    load_stage(1, 1);
    load_stage(2, 2);

    for (int kt = 0; kt < nk; kt++) {
        const int rem = nk - 1 - kt;
        if (rem >= 2) { CP_WAIT2(); } else if (rem == 1) { CP_WAIT1(); } else { CP_WAIT0(); }
        __syncthreads();

        const char* st = sm + (size_t)(kt & 3) * STG;
        const char* Ah_s = st + OFF_AH;
        const char* Al_s = st + OFF_AL;
        const char* Bh_s = st + OFF_BH;
        const char* Bl_s = st + OFF_BL;
        const float* A32s = (const float*)(st + OFF_A32);
        const float* B32s = (const float*)(st + OFF_B32);

#pragma unroll
        for (int ks = 0; ks < 2; ks++) {
            const int kb = ks * 32 + tq * 4;
            uint32_t ah[4][4], al[4][4], bh[3][2], bl[3][2];
#pragma unroll
            for (int mi = 0; mi < 4; mi++) {
                const int r = wm * 64 + mi * 16 + gid;
                const char* p0 = Ah_s + r * PB + kb;
                const char* p1 = Al_s + r * PB + kb;
                ah[mi][0] = *(const uint32_t*)(p0);
                ah[mi][1] = *(const uint32_t*)(p0 + 8 * PB);
                ah[mi][2] = *(const uint32_t*)(p0 + 16);
                ah[mi][3] = *(const uint32_t*)(p0 + 8 * PB + 16);
                al[mi][0] = *(const uint32_t*)(p1);
                al[mi][1] = *(const uint32_t*)(p1 + 8 * PB);
                al[mi][2] = *(const uint32_t*)(p1 + 16);
                al[mi][3] = *(const uint32_t*)(p1 + 8 * PB + 16);
            }
#pragma unroll
            for (int ni = 0; ni < 3; ni++) {
                const int nrow = wn * 24 + ni * 8 + gid;
                const char* p0 = Bh_s + nrow * PB + kb;
                const char* p1 = Bl_s + nrow * PB + kb;
                bh[ni][0] = *(const uint32_t*)(p0);
                bh[ni][1] = *(const uint32_t*)(p0 + 16);
                bl[ni][0] = *(const uint32_t*)(p1);
                bl[ni][1] = *(const uint32_t*)(p1 + 16);
            }
#pragma unroll
            for (int mi = 0; mi < 4; mi++)
#pragma unroll
                for (int ni = 0; ni < 3; ni++)
                    MMA_F16(cc[mi][ni][0], cc[mi][ni][1], cc[mi][ni][2], cc[mi][ni][3],
                            ah[mi][0], ah[mi][1], ah[mi][2], ah[mi][3],
                            bh[ni][0], bh[ni][1]);
#pragma unroll
            for (int mi = 0; mi < 4; mi++)
#pragma unroll
                for (int ni = 0; ni < 3; ni++)
                    MMA_F16(s2[mi][ni][0], s2[mi][ni][1], s2[mi][ni][2], s2[mi][ni][3],
                            ah[mi][0], ah[mi][1], ah[mi][2], ah[mi][3],
                            bl[ni][0], bl[ni][1]);
#pragma unroll
            for (int mi = 0; mi < 4; mi++)
#pragma unroll
                for (int ni = 0; ni < 3; ni++)
                    MMA_F16(s2[mi][ni][0], s2[mi][ni][1], s2[mi][ni][2], s2[mi][ni][3],
                            al[mi][0], al[mi][1], al[mi][2], al[mi][3],
                            bh[ni][0], bh[ni][1]);
        }

        // FFMA sub-GEMM for cols 96..127 (fp32), overlaps with draining MMA pipe
#pragma unroll 8
        for (int k = 0; k < 32; k++) {
            const float4 av = *(const float4*)(A32s + k * 128 + fr0);
            const float4 bv = *(const float4*)(B32s + k * 32 + fc0);
            fa[0][0] = fmaf(av.x, bv.x, fa[0][0]); fa[0][1] = fmaf(av.x, bv.y, fa[0][1]);
            fa[0][2] = fmaf(av.x, bv.z, fa[0][2]); fa[0][3] = fmaf(av.x, bv.w, fa[0][3]);
            fa[1][0] = fmaf(av.y, bv.x, fa[1][0]); fa[1][1] = fmaf(av.y, bv.y, fa[1][1]);
            fa[1][2] = fmaf(av.y, bv.z, fa[1][2]); fa[1][3] = fmaf(av.y, bv.w, fa[1][3]);
            fa[2][0] = fmaf(av.z, bv.x, fa[2][0]); fa[2][1] = fmaf(av.z, bv.y, fa[2][1]);
            fa[2][2] = fmaf(av.z, bv.z, fa[2][2]); fa[2][3] = fmaf(av.z, bv.w, fa[2][3]);
            fa[3][0] = fmaf(av.w, bv.x, fa[3][0]); fa[3][1] = fmaf(av.w, bv.y, fa[3][1]);
            fa[3][2] = fmaf(av.w, bv.z, fa[3][2]); fa[3][3] = fmaf(av.w, bv.w, fa[3][3]);
        }

        if (kt + 3 < nk) load_stage(kt + 3, (kt + 3) & 3);
    }

    // ---- epilogue: stage full 128x128 activated tile in smem, then coalesced writes ----
    __syncthreads();
    float* smf = (float*)sm;   // [128][129]

    // tensor region (cols 0..95)
#pragma unroll
    for (int mi = 0; mi < 4; mi++) {
        const int rl0 = wm * 64 + mi * 16 + gid;
#pragma unroll
        for (int ni = 0; ni < 3; ni++) {
            const int coll = wn * 24 + ni * 8 + tq * 2;
            const float bb0 = __ldg(bias + n0 + coll);
            const float bb1 = __ldg(bias + n0 + coll + 1);
            float v00 = fmaf(s2[mi][ni][0], RSCALE_I, cc[mi][ni][0]) + bb0;
            float v01 = fmaf(s2[mi][ni][1], RSCALE_I, cc[mi][ni][1]) + bb1;
            float v10 = fmaf(s2[mi][ni][2], RSCALE_I, cc[mi][ni][2]) + bb0;
            float v11 = fmaf(s2[mi][ni][3], RSCALE_I, cc[mi][ni][3]) + bb1;
            smf[rl0 * 129 + coll]           = (EPI == 0) ? gelu_f(v00) : sig2_f(v00);
            smf[rl0 * 129 + coll + 1]       = (EPI == 0) ? gelu_f(v01) : sig2_f(v01);
            smf[(rl0 + 8) * 129 + coll]     = (EPI == 0) ? gelu_f(v10) : sig2_f(v10);
            smf[(rl0 + 8) * 129 + coll + 1] = (EPI == 0) ? gelu_f(v11) : sig2_f(v11);
        }
    }
    // FFMA region (cols 96..127)
#pragma unroll
    for (int i = 0; i < 4; i++)
#pragma unroll
        for (int j = 0; j < 4; j++) {
            const int coll = 96 + fc0 + j;
            const float v = fa[i][j] + __ldg(bias + n0 + coll);
            smf[(fr0 + i) * 129 + coll] = (EPI == 0) ? gelu_f(v) : sig2_f(v);
        }
    __syncthreads();

    if (EPI == 0) {
        // hi/lo fp16 planes
        for (int idx = tid; idx < 8192; idx += 256) {
            const int row = idx >> 6;
            const int col = (idx & 63) * 2;
            const float g0 = smf[row * 129 + col];
            const float g1 = smf[row * 129 + col + 1];
            const __half h0 = __float2half_rn(g0), h1 = __float2half_rn(g1);
            __half2 hh; hh.x = h0; hh.y = h1;
            __half2 ll;
            ll.x = __float2half_rn((g0 - __half2float(h0)) * RSCALE);
            ll.y = __float2half_rn((g1 - __half2float(h1)) * RSCALE);
            *(__half2*)(Ohi + (size_t)(m0 + row) * N + n0 + col) = hh;
            *(__half2*)(Olo + (size_t)(m0 + row) * N + n0 + col) = ll;
        }
        // transposed fp32 activations: Oht[N][BROWS]
        for (int c = warp; c < 128; c += 8) {
            float* dst = Oht + (size_t)(n0 + c) * BROWS + m0;
#pragma unroll
            for (int rr = 0; rr < 4; rr++)
                dst[rr * 32 + lane] = smf[(rr * 32 + lane) * 129 + c];
        }
    } else {
        // coeff fp32
        for (int idx = tid; idx < 8192; idx += 256) {
            const int row = idx >> 6;
            const int col = (idx & 63) * 2;
            *(float2*)(Oc + (size_t)(m0 + row) * N + n0 + col) =
                make_float2(smf[row * 129 + col], smf[row * 129 + col + 1]);
        }
        // per-group top-2: one thread per (row, group)
        const int r   = tid & 127;
        const int grp = tid >> 7;
        const float* p = smf + r * 129 + grp * 64;
        float v1 = -1e30f, v2 = -1e30f;
        int i1 = 0, i2 = 0;
#pragma unroll 8
        for (int i = 0; i < POOL; i++) {
            float v = p[i];
            if (v > v1) { v2 = v1; i2 = i1; v1 = v; i1 = i; }
            else if (v > v2) { v2 = v; i2 = i; }
        }
        const size_t o = (size_t)(m0 + r) * (NGRP * TOPK) + ((n0 >> 6) + grp) * TOPK;
        Tv[o] = v1; Tv[o + 1] = v2;
        Ti[o] = (float)i1; Ti[o + 1] = (float)i2;
    }
}

// ---------------- prepass: fp32 -> hi/lo fp16 planes ----------------
__global__ void split16_kernel(const float4* __restrict__ in,
                               __half* __restrict__ hi, __half* __restrict__ lo, int n4) {
    int i = blockIdx.x * blockDim.x + threadIdx.x;
    if (i < n4) {
        float4 v = in[i];
        __half h0 = __float2half_rn(v.x), h1 = __float2half_rn(v.y);
        __half h2 = __float2half_rn(v.z), h3 = __float2half_rn(v.w);
        __half2 ha; ha.x = h0; ha.y = h1;
        __half2 hb; hb.x = h2; hb.y = h3;
        *(__half2*)(hi + 4 * (size_t)i)     = ha;
        *(__half2*)(hi + 4 * (size_t)i + 2) = hb;
        __half2 la, lb;
        la.x = __float2half_rn((v.x - __half2float(h0)) * RSCALE);
        la.y = __float2half_rn((v.y - __half2float(h1)) * RSCALE);
        lb.x = __float2half_rn((v.z - __half2float(h2)) * RSCALE);
        lb.y = __float2half_rn((v.w - __half2float(h3)) * RSCALE);
        *(__half2*)(lo + 4 * (size_t)i)     = la;
        *(__half2*)(lo + 4 * (size_t)i + 2) = lb;
    }
}

// ---------------- prepass: transpose fp32 [M][K] -> [K][M] ----------------
__global__ void t32_kernel(const float* __restrict__ in, float* __restrict__ out,
                           int M, int K) {
    __shared__ float t[32][33];
    const int kb = blockIdx.x * 32, mb = blockIdx.y * 32;
    const int tx = threadIdx.x, ty = threadIdx.y;
#pragma unroll
    for (int r = ty; r < 32; r += 8)
        t[r][tx] = in[(size_t)(mb + r) * K + kb + tx];
    __syncthreads();
#pragma unroll
    for (int r = ty; r < 32; r += 8)
        out[(size_t)(kb + r) * M + mb + tx] = t[tx][r];
}

// ---------------- prepass: W[K,N] fp32 -> Wt hi/lo [N][K] fp16 ----------------
__global__ void tsplit16_kernel(const float* __restrict__ W,
                                __half* __restrict__ hi, __half* __restrict__ lo,
                                int K, int N) {
    __shared__ float t[64][33];
    const int nb = blockIdx.x * 32, kb = blockIdx.y * 64;
    const int tx = threadIdx.x, ty = threadIdx.y;
#pragma unroll
    for (int r = ty; r < 64; r += 8)
        t[r][tx] = W[(size_t)(kb + r) * N + nb + tx];
    __syncthreads();
#pragma unroll
    for (int n = ty; n < 32; n += 8) {
        const float v0 = t[2 * tx][n];
        const float v1 = t[2 * tx + 1][n];
        const __half h0 = __float2half_rn(v0);
        const __half h1 = __float2half_rn(v1);
        __half2 hh; hh.x = h0; hh.y = h1;
        __half2 ll;
        ll.x = __float2half_rn((v0 - __half2float(h0)) * RSCALE);
        ll.y = __float2half_rn((v1 - __half2float(h1)) * RSCALE);
        const size_t base = (size_t)(nb + n) * K + kb + 2 * tx;
        *(__half2*)(hi + base) = hh;
        *(__half2*)(lo + base) = ll;
    }
}

// ---------------- launch ----------------
extern "C" void kernel_launch(void* const* d_in, const int* in_sizes, int n_in,
                              void* d_out, int out_size)
{
    const float* q  = (const float*)d_in[0];
    const float* W1 = (const float*)d_in[1];
    const float* b1 = (const float*)d_in[2];
    const float* W2 = (const float*)d_in[3];
    const float* b2 = (const float*)d_in[4];
    const float* W3 = (const float*)d_in[5];
    const float* b3 = (const float*)d_in[6];
    float* out = (float*)d_out;

    static bool configured = false;
    static __half *qh, *ql, *w1h, *w1l, *w2h, *w2l, *w3h, *w3l, *h1h, *h1l, *h2h, *h2l;
    static float *qt32, *h1t, *h2t;
    if (!configured) {
        cudaGetSymbolAddress((void**)&qh,  g_qh);  cudaGetSymbolAddress((void**)&ql,  g_ql);
        cudaGetSymbolAddress((void**)&w1h, g_w1h); cudaGetSymbolAddress((void**)&w1l, g_w1l);
        cudaGetSymbolAddress((void**)&w2h, g_w2h); cudaGetSymbolAddress((void**)&w2l, g_w2l);
        cudaGetSymbolAddress((void**)&w3h, g_w3h); cudaGetSymbolAddress((void**)&w3l, g_w3l);
        cudaGetSymbolAddress((void**)&h1h, g_h1h); cudaGetSymbolAddress((void**)&h1l, g_h1l);
        cudaGetSymbolAddress((void**)&h2h, g_h2h); cudaGetSymbolAddress((void**)&h2l, g_h2l);
        cudaGetSymbolAddress((void**)&qt32, g_qt32);
        cudaGetSymbolAddress((void**)&h1t, g_h1t);
        cudaGetSymbolAddress((void**)&h2t, g_h2t);
        cudaFuncSetAttribute(gemm_hy<0>, cudaFuncAttributeMaxDynamicSharedMemorySize, GSMEM);
        cudaFuncSetAttribute(gemm_hy<1>, cudaFuncAttributeMaxDynamicSharedMemorySize, GSMEM);
        configured = true;
    }

    float* tv = out + (size_t)BROWS * ODIM;
    float* ti = tv + (size_t)BROWS * NGRP * TOPK;

    // 1) prepasses
    {
        int n4 = (BROWS * INDIM) / 4;
        split16_kernel<<<(n4 + 255) / 256, 256>>>((const float4*)q, qh, ql, n4);
    }
    dim3 tb(32, 8);
    t32_kernel<<<dim3(INDIM / 32, BROWS / 32), tb>>>(q, qt32, BROWS, INDIM);
    tsplit16_kernel<<<dim3(HID / 32, INDIM / 64), tb>>>(W1, w1h, w1l, INDIM, HID);
    tsplit16_kernel<<<dim3(HID / 32, HID / 64),  tb>>>(W2, w2h, w2l, HID,  HID);
    tsplit16_kernel<<<dim3(ODIM / 32, HID / 64), tb>>>(W3, w3h, w3l, HID,  ODIM);

    // 2) three hybrid GEMMs
    dim3 blk(256);
    gemm_hy<0><<<dim3(HID / 128, BROWS / 128), blk, GSMEM>>>(
        qh, ql, w1h, w1l, qt32, W1, b1,
        h1h, h1l, h1t, nullptr, nullptr, nullptr, HID, INDIM, INDIM / 32);
    gemm_hy<0><<<dim3(HID / 128, BROWS / 128), blk, GSMEM>>>(
        h1h, h1l, w2h, w2l, h1t, W2, b2,
        h2h, h2l, h2t, nullptr, nullptr, nullptr, HID, HID, HID / 32);
    gemm_hy<1><<<dim3(ODIM / 128, BROWS / 128), blk, GSMEM>>>(
        h2h, h2l, w3h, w3l, h2t, W3, b3,
        nullptr, nullptr, nullptr, out, tv, ti, ODIM, HID, HID / 32);
}